// round 2
// baseline (speedup 1.0000x reference)
#include <cuda_runtime.h>
#include <math.h>

#define N_NODES 8192
#define DIN     512
#define DOUT    256
#define MAXN    512    // max neighbors stored per row (actual max ~70)

// Scratch (device globals: allocation-free per harness rules)
__device__ float g_h[(size_t)N_NODES * DOUT];        // 8 MB
__device__ float g_g1[N_NODES];
__device__ float g_g2[N_NODES];
__device__ int   g_nbr[(size_t)N_NODES * MAXN];      // 16 MB neighbor lists
__device__ int   g_deg[N_NODES];

// ---------------------------------------------------------------------------
// Packed fp32x2 helpers (FFMA2 — only reachable via explicit PTX)
// ---------------------------------------------------------------------------
__device__ __forceinline__ unsigned long long pk2(float lo, float hi) {
    unsigned long long r;
    asm("mov.b64 %0, {%1, %2};" : "=l"(r)
        : "r"(__float_as_uint(lo)), "r"(__float_as_uint(hi)));
    return r;
}
__device__ __forceinline__ void fma2(unsigned long long& d,
                                     unsigned long long a,
                                     unsigned long long b) {
    asm("fma.rn.f32x2 %0, %1, %2, %0;" : "+l"(d) : "l"(a), "l"(b));
}
__device__ __forceinline__ void upk2(unsigned long long v, float& lo, float& hi) {
    unsigned ulo, uhi;
    asm("mov.b64 {%0, %1}, %2;" : "=r"(ulo), "=r"(uhi) : "l"(v));
    lo = __uint_as_float(ulo);
    hi = __uint_as_float(uhi);
}

// ---------------------------------------------------------------------------
// Fused kernel: blocks [0,128) do the GEMM  h = elu(x)@W1 + b1
//               blocks [128, 128+8192) scan one adjacency row each and emit
//               neighbor index lists (independent of the GEMM -> overlap).
// GEMM tile: 128(M) x 128(N), BK=16, 256 threads, 8x8 per thread via FFMA2.
// ---------------------------------------------------------------------------
#define BM 128
#define BN 128
#define BK 16
#define N_GEMM_BLOCKS 128   // (8192/128) * (256/128) = 64*2

__global__ void __launch_bounds__(256, 2)
fused_gemm_scan_kernel(const float* __restrict__ X,
                       const float* __restrict__ W,
                       const float* __restrict__ b,
                       const float* __restrict__ adj)
{
    __shared__ float As[BK][BM];   // transposed A tile
    __shared__ float Bs[BK][BN];
    __shared__ int   s_cnt;

    const int t = threadIdx.x;

    if (blockIdx.x < N_GEMM_BLOCKS) {
        // ================= GEMM path =================
        const int blk = blockIdx.x;
        const int m0 = (blk >> 1) * BM;
        const int n0 = (blk & 1) * BN;
        const int tx = t & 15;        // col group: 8 cols each
        const int ty = t >> 4;        // row group: 8 rows each

        unsigned long long acc2[8][4];   // [row i][col-pair q] -> cols (2q,2q+1)
        const unsigned long long z = pk2(0.f, 0.f);
#pragma unroll
        for (int i = 0; i < 8; i++)
#pragma unroll
            for (int q = 0; q < 4; q++) acc2[i][q] = z;

        for (int kt = 0; kt < DIN; kt += BK) {
            // Load A tile (128 rows x 16 k), apply ELU, store transposed.
#pragma unroll
            for (int u = 0; u < 2; u++) {
                int f = t + u * 256;
                int i = f >> 2;             // row in tile 0..127
                int j = (f & 3) << 2;       // k offset 0,4,8,12
                float4 v = *(const float4*)(X + (size_t)(m0 + i) * DIN + kt + j);
                v.x = v.x > 0.f ? v.x : expm1f(v.x);
                v.y = v.y > 0.f ? v.y : expm1f(v.y);
                v.z = v.z > 0.f ? v.z : expm1f(v.z);
                v.w = v.w > 0.f ? v.w : expm1f(v.w);
                As[j + 0][i] = v.x;
                As[j + 1][i] = v.y;
                As[j + 2][i] = v.z;
                As[j + 3][i] = v.w;
            }
            // Load B tile (16 k x 128 cols).
#pragma unroll
            for (int u = 0; u < 2; u++) {
                int f = t + u * 256;
                int r = f >> 5;             // k row 0..15
                int c = (f & 31) << 2;      // col 0..124
                *(float4*)&Bs[r][c] =
                    *(const float4*)(W + (size_t)(kt + r) * DOUT + n0 + c);
            }
            __syncthreads();

#pragma unroll
            for (int kk = 0; kk < BK; kk++) {
                float a[8], bb[8];
                *(float4*)(a + 0)  = *(const float4*)&As[kk][ty * 8 + 0];
                *(float4*)(a + 4)  = *(const float4*)&As[kk][ty * 8 + 4];
                *(float4*)(bb + 0) = *(const float4*)&Bs[kk][tx * 8 + 0];
                *(float4*)(bb + 4) = *(const float4*)&Bs[kk][tx * 8 + 4];

                unsigned long long bp[4], ad[8];
#pragma unroll
                for (int q = 0; q < 4; q++) bp[q] = pk2(bb[2 * q], bb[2 * q + 1]);
#pragma unroll
                for (int i = 0; i < 8; i++) ad[i] = pk2(a[i], a[i]);
#pragma unroll
                for (int i = 0; i < 8; i++)
#pragma unroll
                    for (int q = 0; q < 4; q++)
                        fma2(acc2[i][q], ad[i], bp[q]);
            }
            __syncthreads();
        }

        // Epilogue: + bias, write h
        float4 bias0 = *(const float4*)(b + n0 + tx * 8 + 0);
        float4 bias1 = *(const float4*)(b + n0 + tx * 8 + 4);
#pragma unroll
        for (int i = 0; i < 8; i++) {
            float c0, c1, c2, c3, c4, c5, c6, c7;
            upk2(acc2[i][0], c0, c1);
            upk2(acc2[i][1], c2, c3);
            upk2(acc2[i][2], c4, c5);
            upk2(acc2[i][3], c6, c7);
            float4 o0, o1;
            o0.x = c0 + bias0.x; o0.y = c1 + bias0.y;
            o0.z = c2 + bias0.z; o0.w = c3 + bias0.w;
            o1.x = c4 + bias1.x; o1.y = c5 + bias1.y;
            o1.z = c6 + bias1.z; o1.w = c7 + bias1.w;
            float* hrow = g_h + (size_t)(m0 + ty * 8 + i) * DOUT + n0 + tx * 8;
            *(float4*)(hrow + 0) = o0;
            *(float4*)(hrow + 4) = o1;
        }
    } else {
        // ================= adjacency scan path =================
        const int i = blockIdx.x - N_GEMM_BLOCKS;   // row

        if (t == 0) s_cnt = 0;
        __syncthreads();

        const float4* row = (const float4*)(adj + (size_t)i * N_NODES);
        int* nbr = g_nbr + (size_t)i * MAXN;

#pragma unroll
        for (int u = 0; u < 8; u++) {
            int f = t + u * 256;           // float4 index
            float4 v = row[f];
            int jb = f << 2;
            if (v.x > 0.f) { int p = atomicAdd(&s_cnt, 1); if (p < MAXN) nbr[p] = jb + 0; }
            if (v.y > 0.f) { int p = atomicAdd(&s_cnt, 1); if (p < MAXN) nbr[p] = jb + 1; }
            if (v.z > 0.f) { int p = atomicAdd(&s_cnt, 1); if (p < MAXN) nbr[p] = jb + 2; }
            if (v.w > 0.f) { int p = atomicAdd(&s_cnt, 1); if (p < MAXN) nbr[p] = jb + 3; }
        }
        __syncthreads();
        if (t == 0) g_deg[i] = s_cnt < MAXN ? s_cnt : MAXN;
    }
}

// ---------------------------------------------------------------------------
// Kernel G: g1[i] = h[i]·a1_w + a1_b ; g2[i] = h[i]·a2_w + a2_b
// ---------------------------------------------------------------------------
__global__ void g_kernel(const float* __restrict__ a1w, const float* __restrict__ a1b,
                         const float* __restrict__ a2w, const float* __restrict__ a2b)
{
    int warp = threadIdx.x >> 5;
    int lane = threadIdx.x & 31;
    int r = blockIdx.x * 8 + warp;
    const float* hr = g_h + (size_t)r * DOUT;
    float s1 = 0.f, s2 = 0.f;
#pragma unroll
    for (int c = lane; c < DOUT; c += 32) {
        float hv = hr[c];
        s1 = fmaf(hv, a1w[c], s1);
        s2 = fmaf(hv, a2w[c], s2);
    }
#pragma unroll
    for (int o = 16; o; o >>= 1) {
        s1 += __shfl_xor_sync(0xffffffffu, s1, o);
        s2 += __shfl_xor_sync(0xffffffffu, s2, o);
    }
    if (lane == 0) {
        g_g1[r] = s1 + a1b[0];
        g_g2[r] = s2 + a2b[0];
    }
}

// ---------------------------------------------------------------------------
// Aggregation kernel: per-row softmax over neighbor scores + weighted sum of h.
// One block (256 threads) per row; thread t = output channel.
// ---------------------------------------------------------------------------
__global__ void __launch_bounds__(256)
agg_kernel(float* __restrict__ out)
{
    __shared__ float s_e[MAXN];
    __shared__ int   s_j[MAXN];
    __shared__ float red[256];

    const int i = blockIdx.x;
    const int t = threadIdx.x;
    const int deg = g_deg[i];

    if (deg == 0) {
        // softmax over all -9e15 is uniform -> output = column-mean of h
        float acc = 0.f;
        for (int r = 0; r < N_NODES; r++) acc += g_h[(size_t)r * DOUT + t];
        out[(size_t)i * DOUT + t] = acc * (1.f / (float)N_NODES);
        return;
    }

    const float g2i = g_g2[i];
    const int* nbr = g_nbr + (size_t)i * MAXN;

    for (int k = t; k < deg; k += 256) {
        int j = nbr[k];
        s_j[k] = j;
        float s = g2i + g_g1[j];
        s_e[k] = s > 0.f ? s : 0.2f * s;   // leaky_relu(0.2)
    }
    __syncthreads();

    // --- row max ---
    float m = -INFINITY;
    for (int k = t; k < deg; k += 256) m = fmaxf(m, s_e[k]);
    red[t] = m;
    __syncthreads();
#pragma unroll
    for (int o = 128; o; o >>= 1) {
        if (t < o) red[t] = fmaxf(red[t], red[t + o]);
        __syncthreads();
    }
    const float rowmax = red[0];
    __syncthreads();

    // --- exp + sum ---
    float ssum = 0.f;
    for (int k = t; k < deg; k += 256) {
        float w = __expf(s_e[k] - rowmax);
        s_e[k] = w;
        ssum += w;
    }
    red[t] = ssum;
    __syncthreads();
#pragma unroll
    for (int o = 128; o; o >>= 1) {
        if (t < o) red[t] += red[t + o];
        __syncthreads();
    }
    const float inv = 1.f / red[0];

    // --- aggregation: thread t = output channel, 4 parallel accumulators ---
    float a0 = 0.f, a1 = 0.f, a2 = 0.f, a3 = 0.f;
    int k = 0;
    for (; k + 4 <= deg; k += 4) {
        a0 = fmaf(s_e[k + 0], g_h[(size_t)s_j[k + 0] * DOUT + t], a0);
        a1 = fmaf(s_e[k + 1], g_h[(size_t)s_j[k + 1] * DOUT + t], a1);
        a2 = fmaf(s_e[k + 2], g_h[(size_t)s_j[k + 2] * DOUT + t], a2);
        a3 = fmaf(s_e[k + 3], g_h[(size_t)s_j[k + 3] * DOUT + t], a3);
    }
    for (; k < deg; k++)
        a0 = fmaf(s_e[k], g_h[(size_t)s_j[k] * DOUT + t], a0);

    out[(size_t)i * DOUT + t] = (a0 + a1 + a2 + a3) * inv;
}

// ---------------------------------------------------------------------------
extern "C" void kernel_launch(void* const* d_in, const int* in_sizes, int n_in,
                              void* d_out, int out_size)
{
    const float* x   = (const float*)d_in[0];   // [8192, 512]
    const float* adj = (const float*)d_in[1];   // [8192, 8192]
    const float* W1  = (const float*)d_in[2];   // [512, 256]
    const float* b1  = (const float*)d_in[3];   // [256]
    const float* a1w = (const float*)d_in[4];   // [256]
    const float* a1b = (const float*)d_in[5];   // scalar
    const float* a2w = (const float*)d_in[6];   // [256]
    const float* a2b = (const float*)d_in[7];   // scalar
    float* out = (float*)d_out;                 // [8192, 256]

    fused_gemm_scan_kernel<<<N_GEMM_BLOCKS + N_NODES, 256>>>(x, W1, b1, adj);
    g_kernel<<<N_NODES / 8, 256>>>(a1w, a1b, a2w, a2b);
    agg_kernel<<<N_NODES, 256>>>(out);
}

// round 3
// speedup vs baseline: 1.0939x; 1.0939x over previous
#include <cuda_runtime.h>
#include <math.h>

#define N_NODES 8192
#define DIN     512
#define DOUT    256
#define MAXN    512    // max neighbors stored per row (actual max ~60)

// Scratch (device globals: allocation-free per harness rules)
__device__ float g_h[(size_t)N_NODES * DOUT];   // 8 MB
__device__ float g_g1[N_NODES];
__device__ float g_g2[N_NODES];

// ---------------------------------------------------------------------------
// Packed fp32x2 helpers (FFMA2 — only reachable via explicit PTX)
// ---------------------------------------------------------------------------
__device__ __forceinline__ void fma2(unsigned long long& d,
                                     unsigned long long a,
                                     unsigned long long b) {
    asm("fma.rn.f32x2 %0, %1, %2, %0;" : "+l"(d) : "l"(a), "l"(b));
}
__device__ __forceinline__ void upk2(unsigned long long v, float& lo, float& hi) {
    unsigned ulo, uhi;
    asm("mov.b64 {%0, %1}, %2;" : "=r"(ulo), "=r"(uhi) : "l"(v));
    lo = __uint_as_float(ulo);
    hi = __uint_as_float(uhi);
}
__device__ __forceinline__ void lds_v2u64(unsigned long long& x, unsigned long long& y,
                                          unsigned addr) {
    asm volatile("ld.shared.v2.u64 {%0, %1}, [%2];" : "=l"(x), "=l"(y) : "r"(addr));
}
__device__ __forceinline__ unsigned long long lds_u64(unsigned addr) {
    unsigned long long x;
    asm volatile("ld.shared.u64 %0, [%1];" : "=l"(x) : "r"(addr));
    return x;
}

// ---------------------------------------------------------------------------
// GEMM: h = elu(x) @ W1 + b1    (M=8192, K=512, N=256)
// Tile 128(M) x 128(N), BK=16, 256 threads.
// Thread covers rows ty*8..ty*8+7 (as 4 native 64-bit pairs) and
// cols tx + 16*q, q=0..7. B stored duplicated in smem -> (b,b) via LDS.64.
// ---------------------------------------------------------------------------
#define BM 128
#define BN 128
#define BK 16
#define AS_STRIDE 132                  // floats per As row (pad, 16B-aligned)

__global__ void __launch_bounds__(256, 2)
gemm_elu_kernel(const float* __restrict__ X,
                const float* __restrict__ W,
                const float* __restrict__ b)
{
    __shared__ float As[BK][AS_STRIDE];     // As[kk][i] = elu(x[m0+i][kt+kk])
    __shared__ float Bs2[BK][2 * BN];       // Bs2[kk][2c]=Bs2[kk][2c+1]=W[kt+kk][n0+c]

    const int t  = threadIdx.x;
    const int tx = t & 15;
    const int ty = t >> 4;
    const int m0 = blockIdx.y * BM;
    const int n0 = blockIdx.x * BN;

    const unsigned asBase = (unsigned)__cvta_generic_to_shared(&As[0][0]);
    const unsigned bsBase = (unsigned)__cvta_generic_to_shared(&Bs2[0][0]);
    const unsigned aAddr0 = asBase + ty * 32;      // + kk*AS_STRIDE*4
    const unsigned bAddr0 = bsBase + tx * 8;       // + kk*2*BN*4 + q*128

    unsigned long long acc[4][8];
#pragma unroll
    for (int p = 0; p < 4; p++)
#pragma unroll
        for (int q = 0; q < 8; q++) acc[p][q] = 0ull;

    for (int kt = 0; kt < DIN; kt += BK) {
        // ---- load A tile (128 rows x 16 k), ELU, store transposed ----
#pragma unroll
        for (int u = 0; u < 2; u++) {
            int f = t + u * 256;
            int i = f >> 2;              // row 0..127
            int j = (f & 3) << 2;        // k 0,4,8,12
            float4 v = *(const float4*)(X + (size_t)(m0 + i) * DIN + kt + j);
            v.x = v.x > 0.f ? v.x : expm1f(v.x);
            v.y = v.y > 0.f ? v.y : expm1f(v.y);
            v.z = v.z > 0.f ? v.z : expm1f(v.z);
            v.w = v.w > 0.f ? v.w : expm1f(v.w);
            As[j + 0][i] = v.x;
            As[j + 1][i] = v.y;
            As[j + 2][i] = v.z;
            As[j + 3][i] = v.w;
        }
        // ---- load B tile (16 k x 128 cols), store duplicated ----
#pragma unroll
        for (int u = 0; u < 2; u++) {
            int f = t + u * 256;
            int r = f >> 5;              // k 0..15
            int c = (f & 31) << 2;       // col 0..124
            float4 w4 = *(const float4*)(W + (size_t)(kt + r) * DOUT + n0 + c);
            *(float2*)&Bs2[r][2 * (c + 0)] = make_float2(w4.x, w4.x);
            *(float2*)&Bs2[r][2 * (c + 1)] = make_float2(w4.y, w4.y);
            *(float2*)&Bs2[r][2 * (c + 2)] = make_float2(w4.z, w4.z);
            *(float2*)&Bs2[r][2 * (c + 3)] = make_float2(w4.w, w4.w);
        }
        __syncthreads();

#pragma unroll
        for (int kk = 0; kk < BK; kk++) {
            unsigned aA = aAddr0 + kk * (AS_STRIDE * 4);
            unsigned bA = bAddr0 + kk * (2 * BN * 4);
            unsigned long long ap[4];
            lds_v2u64(ap[0], ap[1], aA);
            lds_v2u64(ap[2], ap[3], aA + 16);
            unsigned long long bq[8];
#pragma unroll
            for (int q = 0; q < 8; q++) bq[q] = lds_u64(bA + q * 128);
#pragma unroll
            for (int p = 0; p < 4; p++)
#pragma unroll
                for (int q = 0; q < 8; q++)
                    fma2(acc[p][q], ap[p], bq[q]);
        }
        __syncthreads();
    }

    // ---- epilogue: + bias, write h ----
    float bias[8];
#pragma unroll
    for (int q = 0; q < 8; q++) bias[q] = b[n0 + tx + 16 * q];
#pragma unroll
    for (int p = 0; p < 4; p++) {
        float* r0 = g_h + (size_t)(m0 + ty * 8 + 2 * p + 0) * DOUT + n0 + tx;
        float* r1 = g_h + (size_t)(m0 + ty * 8 + 2 * p + 1) * DOUT + n0 + tx;
#pragma unroll
        for (int q = 0; q < 8; q++) {
            float lo, hi;
            upk2(acc[p][q], lo, hi);
            r0[16 * q] = lo + bias[q];
            r1[16 * q] = hi + bias[q];
        }
    }
}

// ---------------------------------------------------------------------------
// Kernel G: g1[i] = h[i]·a1_w + a1_b ; g2[i] = h[i]·a2_w + a2_b
// ---------------------------------------------------------------------------
__global__ void g_kernel(const float* __restrict__ a1w, const float* __restrict__ a1b,
                         const float* __restrict__ a2w, const float* __restrict__ a2b)
{
    int warp = threadIdx.x >> 5;
    int lane = threadIdx.x & 31;
    int r = blockIdx.x * 8 + warp;
    const float* hr = g_h + (size_t)r * DOUT;
    float s1 = 0.f, s2 = 0.f;
#pragma unroll
    for (int c = lane; c < DOUT; c += 32) {
        float hv = hr[c];
        s1 = fmaf(hv, a1w[c], s1);
        s2 = fmaf(hv, a2w[c], s2);
    }
#pragma unroll
    for (int o = 16; o; o >>= 1) {
        s1 += __shfl_xor_sync(0xffffffffu, s1, o);
        s2 += __shfl_xor_sync(0xffffffffu, s2, o);
    }
    if (lane == 0) {
        g_g1[r] = s1 + a1b[0];
        g_g2[r] = s2 + a2b[0];
    }
}

// ---------------------------------------------------------------------------
// attn kernel: per-row adjacency scan + masked softmax + weighted aggregation.
// One block (256 threads) per row. Warp 0 does the reductions (deg << 256).
// ---------------------------------------------------------------------------
__global__ void __launch_bounds__(256)
attn_kernel(const float* __restrict__ adj, float* __restrict__ out)
{
    __shared__ int   s_idx[MAXN];
    __shared__ float s_e[MAXN];
    __shared__ int   s_cnt;
    __shared__ float s_inv;

    const int i = blockIdx.x;
    const int t = threadIdx.x;

    if (t == 0) s_cnt = 0;
    __syncthreads();

    const float g2i = g_g2[i];
    const float4* row = (const float4*)(adj + (size_t)i * N_NODES);

#pragma unroll
    for (int u = 0; u < 8; u++) {
        int f = t + u * 256;             // float4 index
        float4 v = row[f];
        int jb = f << 2;
        if (v.x > 0.f) { int p = atomicAdd(&s_cnt, 1); if (p < MAXN) { float s = g2i + g_g1[jb + 0]; s_idx[p] = jb + 0; s_e[p] = s > 0.f ? s : 0.2f * s; } }
        if (v.y > 0.f) { int p = atomicAdd(&s_cnt, 1); if (p < MAXN) { float s = g2i + g_g1[jb + 1]; s_idx[p] = jb + 1; s_e[p] = s > 0.f ? s : 0.2f * s; } }
        if (v.z > 0.f) { int p = atomicAdd(&s_cnt, 1); if (p < MAXN) { float s = g2i + g_g1[jb + 2]; s_idx[p] = jb + 2; s_e[p] = s > 0.f ? s : 0.2f * s; } }
        if (v.w > 0.f) { int p = atomicAdd(&s_cnt, 1); if (p < MAXN) { float s = g2i + g_g1[jb + 3]; s_idx[p] = jb + 3; s_e[p] = s > 0.f ? s : 0.2f * s; } }
    }
    __syncthreads();

    const int cnt = s_cnt < MAXN ? s_cnt : MAXN;

    if (cnt == 0) {
        // softmax over all -9e15 is uniform -> output = column-mean of h
        float acc = 0.f;
        for (int r = 0; r < N_NODES; r++) acc += g_h[(size_t)r * DOUT + t];
        out[(size_t)i * DOUT + t] = acc * (1.f / (float)N_NODES);
        return;   // whole block takes this branch together
    }

    // ---- warp 0: max, exp, sum ----
    if (t < 32) {
        float m = -INFINITY;
        for (int k = t; k < cnt; k += 32) m = fmaxf(m, s_e[k]);
#pragma unroll
        for (int o = 16; o; o >>= 1) m = fmaxf(m, __shfl_xor_sync(0xffffffffu, m, o));
        float ssum = 0.f;
        for (int k = t; k < cnt; k += 32) {
            float w = __expf(s_e[k] - m);
            s_e[k] = w;
            ssum += w;
        }
#pragma unroll
        for (int o = 16; o; o >>= 1) ssum += __shfl_xor_sync(0xffffffffu, ssum, o);
        if (t == 0) s_inv = 1.f / ssum;
    }
    __syncthreads();

    // ---- aggregation: thread t = output channel, 4 parallel accumulators ----
    const float inv = s_inv;
    float a0 = 0.f, a1 = 0.f, a2 = 0.f, a3 = 0.f;
    int k = 0;
    for (; k + 4 <= cnt; k += 4) {
        a0 = fmaf(s_e[k + 0], g_h[(size_t)s_idx[k + 0] * DOUT + t], a0);
        a1 = fmaf(s_e[k + 1], g_h[(size_t)s_idx[k + 1] * DOUT + t], a1);
        a2 = fmaf(s_e[k + 2], g_h[(size_t)s_idx[k + 2] * DOUT + t], a2);
        a3 = fmaf(s_e[k + 3], g_h[(size_t)s_idx[k + 3] * DOUT + t], a3);
    }
    for (; k < cnt; k++)
        a0 = fmaf(s_e[k], g_h[(size_t)s_idx[k] * DOUT + t], a0);

    out[(size_t)i * DOUT + t] = (a0 + a1 + a2 + a3) * inv;
}

// ---------------------------------------------------------------------------
extern "C" void kernel_launch(void* const* d_in, const int* in_sizes, int n_in,
                              void* d_out, int out_size)
{
    const float* x   = (const float*)d_in[0];   // [8192, 512]
    const float* adj = (const float*)d_in[1];   // [8192, 8192]
    const float* W1  = (const float*)d_in[2];   // [512, 256]
    const float* b1  = (const float*)d_in[3];   // [256]
    const float* a1w = (const float*)d_in[4];   // [256]
    const float* a1b = (const float*)d_in[5];   // scalar
    const float* a2w = (const float*)d_in[6];   // [256]
    const float* a2b = (const float*)d_in[7];   // scalar
    float* out = (float*)d_out;                 // [8192, 256]

    dim3 gemm_grid(DOUT / BN, N_NODES / BM);    // (2, 64)
    gemm_elu_kernel<<<gemm_grid, 256>>>(x, W1, b1);
    g_kernel<<<N_NODES / 8, 256>>>(a1w, a1b, a2w, a2b);
    attn_kernel<<<N_NODES, 256>>>(adj, out);
}

// round 5
// speedup vs baseline: 1.5694x; 1.4347x over previous
#include <cuda_runtime.h>
#include <cuda_bf16.h>
#include <math.h>
#include <stdint.h>

#define N_NODES 8192
#define DIN     512
#define DOUT    256
#define MAXN    512

// ---------------------------------------------------------------------------
// Device scratch (globals: allocation-free per harness rules)
// ---------------------------------------------------------------------------
__device__ float g_h[(size_t)N_NODES * DOUT];   // 8 MB
__device__ float g_g1[N_NODES];
__device__ float g_g2[N_NODES];
__device__ __align__(16) __nv_bfloat16 g_ahi[(size_t)N_NODES * DIN];  // 8 MB
__device__ __align__(16) __nv_bfloat16 g_alo[(size_t)N_NODES * DIN];  // 8 MB
__device__ __align__(16) __nv_bfloat16 g_whi[(size_t)DOUT * DIN];     // W^T [n][k]
__device__ __align__(16) __nv_bfloat16 g_wlo[(size_t)DOUT * DIN];

// ---------------------------------------------------------------------------
// PTX helpers
// ---------------------------------------------------------------------------
__device__ __forceinline__ uint32_t smem_u32(const void* p) {
    uint32_t a;
    asm("{ .reg .u64 t; cvta.to.shared.u64 t, %1; cvt.u32.u64 %0, t; }"
        : "=r"(a) : "l"(p));
    return a;
}
__device__ __forceinline__ void cp16(uint32_t dst, const void* src) {
    asm volatile("cp.async.ca.shared.global [%0], [%1], 16;"
                 :: "r"(dst), "l"(src) : "memory");
}
#define CP_COMMIT() asm volatile("cp.async.commit_group;" ::: "memory")
#define CP_WAIT(n)  asm volatile("cp.async.wait_group %0;" :: "n"(n) : "memory")

__device__ __forceinline__ uint32_t lds32(uint32_t addr) {
    uint32_t v;
    asm volatile("ld.shared.b32 %0, [%1];" : "=r"(v) : "r"(addr));
    return v;
}
__device__ __forceinline__ void mma16816(float* d, const uint32_t* a,
                                         const uint32_t* b) {
    asm volatile(
        "mma.sync.aligned.m16n8k16.row.col.f32.bf16.bf16.f32 "
        "{%0,%1,%2,%3}, {%4,%5,%6,%7}, {%8,%9}, {%0,%1,%2,%3};"
        : "+f"(d[0]), "+f"(d[1]), "+f"(d[2]), "+f"(d[3])
        : "r"(a[0]), "r"(a[1]), "r"(a[2]), "r"(a[3]), "r"(b[0]), "r"(b[1]));
}
__device__ __forceinline__ unsigned short bf16b(float v) {
    __nv_bfloat16 h = __float2bfloat16_rn(v);
    return *reinterpret_cast<unsigned short*>(&h);
}

// ---------------------------------------------------------------------------
// Prep A: elu(x) -> bf16 hi/lo, row-major [8192][512].
// ---------------------------------------------------------------------------
__global__ void __launch_bounds__(256)
prep_a_kernel(const float* __restrict__ X)
{
    int T = blockIdx.x * 256 + threadIdx.x;     // 0 .. 524287
    int m  = T >> 6;
    int k0 = (T & 63) << 3;

    float4 v0 = *(const float4*)(X + (size_t)m * DIN + k0);
    float4 v1 = *(const float4*)(X + (size_t)m * DIN + k0 + 4);
    float f[8] = {v0.x, v0.y, v0.z, v0.w, v1.x, v1.y, v1.z, v1.w};

    unsigned short hs[8], ls[8];
#pragma unroll
    for (int i = 0; i < 8; i++) {
        float v = f[i] > 0.f ? f[i] : expm1f(f[i]);
        hs[i] = bf16b(v);
        float hf = __uint_as_float((uint32_t)hs[i] << 16);
        ls[i] = bf16b(v - hf);
    }
    uint4 ph, pl;
    ph.x = hs[0] | ((uint32_t)hs[1] << 16); ph.y = hs[2] | ((uint32_t)hs[3] << 16);
    ph.z = hs[4] | ((uint32_t)hs[5] << 16); ph.w = hs[6] | ((uint32_t)hs[7] << 16);
    pl.x = ls[0] | ((uint32_t)ls[1] << 16); pl.y = ls[2] | ((uint32_t)ls[3] << 16);
    pl.z = ls[4] | ((uint32_t)ls[5] << 16); pl.w = ls[6] | ((uint32_t)ls[7] << 16);

    *(uint4*)(g_ahi + (size_t)m * DIN + k0) = ph;
    *(uint4*)(g_alo + (size_t)m * DIN + k0) = pl;
}

// ---------------------------------------------------------------------------
// Prep W: W[512,256] -> W^T hi/lo bf16 [256 n][512 k].
// ---------------------------------------------------------------------------
__global__ void __launch_bounds__(256)
prep_w_kernel(const float* __restrict__ W)
{
    int T = blockIdx.x * 256 + threadIdx.x;     // 0..16383
    int n  = T >> 6;
    int k0 = (T & 63) << 3;

    unsigned short hs[8], ls[8];
#pragma unroll
    for (int i = 0; i < 8; i++) {
        float v = W[(size_t)(k0 + i) * DOUT + n];
        hs[i] = bf16b(v);
        float hf = __uint_as_float((uint32_t)hs[i] << 16);
        ls[i] = bf16b(v - hf);
    }
    uint4 ph, pl;
    ph.x = hs[0] | ((uint32_t)hs[1] << 16); ph.y = hs[2] | ((uint32_t)hs[3] << 16);
    ph.z = hs[4] | ((uint32_t)hs[5] << 16); ph.w = hs[6] | ((uint32_t)hs[7] << 16);
    pl.x = ls[0] | ((uint32_t)ls[1] << 16); pl.y = ls[2] | ((uint32_t)ls[3] << 16);
    pl.z = ls[4] | ((uint32_t)ls[5] << 16); pl.w = ls[6] | ((uint32_t)ls[7] << 16);

    *(uint4*)(g_whi + (size_t)n * DIN + k0) = ph;
    *(uint4*)(g_wlo + (size_t)n * DIN + k0) = pl;
}

// ---------------------------------------------------------------------------
// mma.sync GEMM: h = A@W^T + b with 3-term bf16 split.
// CTA 128(M) x 128(N), 8 warps (2m x 4n), warp tile 64x32, BK=32.
// smem rows padded to 40 bf16 (80 B) -> conflict-free 32-bit fragment loads.
// 48 stages = 3 terms x 16 k-chunks, cp.async double buffer.
// ---------------------------------------------------------------------------
#define SA 40                       // bf16 per smem row (80 B)
#define STG 10240                   // bytes per 128x40 bf16 tile
#define N_STAGES 48

__global__ void __launch_bounds__(256)
gemm_mma_kernel(const float* __restrict__ b)
{
    __shared__ __align__(16) unsigned char sm[4 * STG];  // As[2] then Bs[2]

    const int t    = threadIdx.x;
    const int wid  = t >> 5;
    const int lane = t & 31;
    const int g    = lane >> 2;     // group 0..7
    const int tl   = lane & 3;      // thread-in-group 0..3
    const int wm0  = (wid >> 2) * 64;
    const int wn0  = (wid & 3) * 32;
    const int m0   = blockIdx.y * 128;
    const int n0   = blockIdx.x * 128;

    const uint32_t sbase = smem_u32(sm);

    float d[4][4][4];
#pragma unroll
    for (int mt = 0; mt < 4; mt++)
#pragma unroll
        for (int nt = 0; nt < 4; nt++)
#pragma unroll
            for (int i = 0; i < 4; i++) d[mt][nt][i] = 0.f;

    // per-thread copy coordinates (2 x 16B for A, 2 x 16B for B per stage)
    const int crow0 = t >> 2;               // 0..63
    const int crow1 = crow0 + 64;
    const int cc    = (t & 3) << 3;         // k element offset 0,8,16,24

    // stage loader
    auto load_stage = [&](int s) {
        const int term = s >> 4;
        const int kt   = (s & 15) << 5;
        const __nv_bfloat16* aS = (term == 1) ? g_alo : g_ahi;
        const __nv_bfloat16* bS = (term == 2) ? g_wlo : g_whi;
        const int buf = s & 1;
        uint32_t aBase = sbase + buf * STG;
        uint32_t bBase = sbase + 2 * STG + buf * STG;
        cp16(aBase + crow0 * (SA * 2) + cc * 2,
             aS + (size_t)(m0 + crow0) * DIN + kt + cc);
        cp16(aBase + crow1 * (SA * 2) + cc * 2,
             aS + (size_t)(m0 + crow1) * DIN + kt + cc);
        cp16(bBase + crow0 * (SA * 2) + cc * 2,
             bS + (size_t)(n0 + crow0) * DIN + kt + cc);
        cp16(bBase + crow1 * (SA * 2) + cc * 2,
             bS + (size_t)(n0 + crow1) * DIN + kt + cc);
    };

    load_stage(0);
    CP_COMMIT();

    for (int s = 0; s < N_STAGES; s++) {
        if (s + 1 < N_STAGES) {
            load_stage(s + 1);
            CP_COMMIT();
            CP_WAIT(1);
        } else {
            CP_WAIT(0);
        }
        __syncthreads();

        const int buf = s & 1;
        const uint32_t aT = sbase + buf * STG + (wm0 + g) * (SA * 2) + tl * 4;
        const uint32_t bT = sbase + 2 * STG + buf * STG + (wn0 + g) * (SA * 2) + tl * 4;

#pragma unroll
        for (int kh = 0; kh < 2; kh++) {
            const uint32_t ko = kh * 32;     // byte offset of k16 half
            uint32_t a[4][4], bb[4][2];
#pragma unroll
            for (int mt = 0; mt < 4; mt++) {
                uint32_t r = aT + mt * (16 * SA * 2) + ko;
                a[mt][0] = lds32(r);
                a[mt][1] = lds32(r + 8 * SA * 2);
                a[mt][2] = lds32(r + 16);
                a[mt][3] = lds32(r + 8 * SA * 2 + 16);
            }
#pragma unroll
            for (int nt = 0; nt < 4; nt++) {
                uint32_t r = bT + nt * (8 * SA * 2) + ko;
                bb[nt][0] = lds32(r);
                bb[nt][1] = lds32(r + 16);
            }
#pragma unroll
            for (int mt = 0; mt < 4; mt++)
#pragma unroll
                for (int nt = 0; nt < 4; nt++)
                    mma16816(d[mt][nt], a[mt], bb[nt]);
        }
        __syncthreads();
    }

    // ---- epilogue: + bias, write h ----
    float2 bias[4];
#pragma unroll
    for (int nt = 0; nt < 4; nt++)
        bias[nt] = *(const float2*)(b + n0 + wn0 + nt * 8 + 2 * tl);

#pragma unroll
    for (int mt = 0; mt < 4; mt++) {
        int row0 = m0 + wm0 + mt * 16 + g;
#pragma unroll
        for (int nt = 0; nt < 4; nt++) {
            int col = n0 + wn0 + nt * 8 + 2 * tl;
            float2 v0 = make_float2(d[mt][nt][0] + bias[nt].x,
                                    d[mt][nt][1] + bias[nt].y);
            float2 v1 = make_float2(d[mt][nt][2] + bias[nt].x,
                                    d[mt][nt][3] + bias[nt].y);
            *(float2*)(g_h + (size_t)row0 * DOUT + col) = v0;
            *(float2*)(g_h + (size_t)(row0 + 8) * DOUT + col) = v1;
        }
    }
}

// ---------------------------------------------------------------------------
// Kernel G: g1[i] = h[i]·a1_w + a1_b ; g2[i] = h[i]·a2_w + a2_b
// ---------------------------------------------------------------------------
__global__ void g_kernel(const float* __restrict__ a1w, const float* __restrict__ a1b,
                         const float* __restrict__ a2w, const float* __restrict__ a2b)
{
    int warp = threadIdx.x >> 5;
    int lane = threadIdx.x & 31;
    int r = blockIdx.x * 8 + warp;
    const float* hr = g_h + (size_t)r * DOUT;
    float s1 = 0.f, s2 = 0.f;
#pragma unroll
    for (int c = lane; c < DOUT; c += 32) {
        float hv = hr[c];
        s1 = fmaf(hv, a1w[c], s1);
        s2 = fmaf(hv, a2w[c], s2);
    }
#pragma unroll
    for (int o = 16; o; o >>= 1) {
        s1 += __shfl_xor_sync(0xffffffffu, s1, o);
        s2 += __shfl_xor_sync(0xffffffffu, s2, o);
    }
    if (lane == 0) {
        g_g1[r] = s1 + a1b[0];
        g_g2[r] = s2 + a2b[0];
    }
}

// ---------------------------------------------------------------------------
// attn kernel: per-row adjacency scan + masked softmax + weighted aggregation.
// ---------------------------------------------------------------------------
__global__ void __launch_bounds__(256)
attn_kernel(const float* __restrict__ adj, float* __restrict__ out)
{
    __shared__ int   s_idx[MAXN];
    __shared__ float s_e[MAXN];
    __shared__ int   s_cnt;
    __shared__ float s_inv;

    const int i = blockIdx.x;
    const int t = threadIdx.x;

    if (t == 0) s_cnt = 0;
    __syncthreads();

    const float g2i = g_g2[i];
    const float4* row = (const float4*)(adj + (size_t)i * N_NODES);

#pragma unroll
    for (int u = 0; u < 8; u++) {
        int f = t + u * 256;
        float4 v = row[f];
        int jb = f << 2;
        if (v.x > 0.f) { int p = atomicAdd(&s_cnt, 1); if (p < MAXN) { float s = g2i + g_g1[jb + 0]; s_idx[p] = jb + 0; s_e[p] = s > 0.f ? s : 0.2f * s; } }
        if (v.y > 0.f) { int p = atomicAdd(&s_cnt, 1); if (p < MAXN) { float s = g2i + g_g1[jb + 1]; s_idx[p] = jb + 1; s_e[p] = s > 0.f ? s : 0.2f * s; } }
        if (v.z > 0.f) { int p = atomicAdd(&s_cnt, 1); if (p < MAXN) { float s = g2i + g_g1[jb + 2]; s_idx[p] = jb + 2; s_e[p] = s > 0.f ? s : 0.2f * s; } }
        if (v.w > 0.f) { int p = atomicAdd(&s_cnt, 1); if (p < MAXN) { float s = g2i + g_g1[jb + 3]; s_idx[p] = jb + 3; s_e[p] = s > 0.f ? s : 0.2f * s; } }
    }
    __syncthreads();

    const int cnt = s_cnt < MAXN ? s_cnt : MAXN;

    if (cnt == 0) {
        float acc = 0.f;
        for (int r = 0; r < N_NODES; r++) acc += g_h[(size_t)r * DOUT + t];
        out[(size_t)i * DOUT + t] = acc * (1.f / (float)N_NODES);
        return;
    }

    if (t < 32) {
        float m = -INFINITY;
        for (int k = t; k < cnt; k += 32) m = fmaxf(m, s_e[k]);
#pragma unroll
        for (int o = 16; o; o >>= 1) m = fmaxf(m, __shfl_xor_sync(0xffffffffu, m, o));
        float ssum = 0.f;
        for (int k = t; k < cnt; k += 32) {
            float w = __expf(s_e[k] - m);
            s_e[k] = w;
            ssum += w;
        }
#pragma unroll
        for (int o = 16; o; o >>= 1) ssum += __shfl_xor_sync(0xffffffffu, ssum, o);
        if (t == 0) s_inv = 1.f / ssum;
    }
    __syncthreads();

    const float inv = s_inv;
    float a0 = 0.f, a1 = 0.f, a2 = 0.f, a3 = 0.f;
    int k = 0;
    for (; k + 4 <= cnt; k += 4) {
        a0 = fmaf(s_e[k + 0], g_h[(size_t)s_idx[k + 0] * DOUT + t], a0);
        a1 = fmaf(s_e[k + 1], g_h[(size_t)s_idx[k + 1] * DOUT + t], a1);
        a2 = fmaf(s_e[k + 2], g_h[(size_t)s_idx[k + 2] * DOUT + t], a2);
        a3 = fmaf(s_e[k + 3], g_h[(size_t)s_idx[k + 3] * DOUT + t], a3);
    }
    for (; k < cnt; k++)
        a0 = fmaf(s_e[k], g_h[(size_t)s_idx[k] * DOUT + t], a0);

    out[(size_t)i * DOUT + t] = (a0 + a1 + a2 + a3) * inv;
}

// ---------------------------------------------------------------------------
extern "C" void kernel_launch(void* const* d_in, const int* in_sizes, int n_in,
                              void* d_out, int out_size)
{
    const float* x   = (const float*)d_in[0];   // [8192, 512]
    const float* adj = (const float*)d_in[1];   // [8192, 8192]
    const float* W1  = (const float*)d_in[2];   // [512, 256]
    const float* b1  = (const float*)d_in[3];   // [256]
    const float* a1w = (const float*)d_in[4];   // [256]
    const float* a1b = (const float*)d_in[5];   // scalar
    const float* a2w = (const float*)d_in[6];   // [256]
    const float* a2b = (const float*)d_in[7];   // scalar
    float* out = (float*)d_out;                 // [8192, 256]

    prep_a_kernel<<<2048, 256>>>(x);
    prep_w_kernel<<<64, 256>>>(W1);
    dim3 gg(DOUT / 128, N_NODES / 128);         // (2, 64)
    gemm_mma_kernel<<<gg, 256>>>(b1);
    g_kernel<<<N_NODES / 8, 256>>>(a1w, a1b, a2w, a2b);
    attn_kernel<<<N_NODES, 256>>>(adj, out);
}